// round 8
// baseline (speedup 1.0000x reference)
#include <cuda_runtime.h>
#include <cstddef>

// KPN per-pixel dynamic convolution, K=15.
// data:    [1, 8, 3, 96, 96]      float32
// kernels: [1, 8, 225, 3, 96, 96] float32   (tap-major: k = i*15 + j)
// out:     [1, 8, 3, 96, 96]      float32
//
// R8 = R2 (best, 35.6us) + warp phase-staggering: each warp starts its
// 5-row tap sequence at a different rotation so per-SM memory requests
// flow smoothly instead of in lockstep bursts. Tile prologue vectorized.

#define KSZ    15
#define PAD    7
#define HH     96
#define WW     96
#define CCH    3
#define TTT    8
#define TILE_H 8
#define ZSPLIT 3                   // 15 tap rows split 5/5/5 across threadIdx.z
#define ROWS_PER_Z (KSZ / ZSPLIT)  // 5
#define SMEM_W 112                 // 96 + 14 halo = 110 -> 112 (16B align)
#define SMEM_H (TILE_H + KSZ - 1)  // 22
#define SLAB   (HH * WW)           // 9216
#define KSTRIDE (CCH * HH * WW)    // 27648 floats between consecutive taps
#define NTHREADS (24 * TILE_H * ZSPLIT)  // 576

__global__ __launch_bounds__(NTHREADS)
void kpn_kernel(const float* __restrict__ data,
                const float* __restrict__ kernels,
                float* __restrict__ out)
{
    __shared__ float tile[SMEM_H * SMEM_W];                       // 9856 B
    __shared__ float part[ZSPLIT - 1][TILE_H][24][4];             // 6144 B

    const int tc = blockIdx.y;             // t*3 + c, 0..23
    const int h0 = blockIdx.x * TILE_H;    // output row base
    const float* dslab = data + (size_t)tc * SLAB;

    const int tx = threadIdx.x;            // 0..23  (w / 4)
    const int ty = threadIdx.y;            // 0..7   (row in tile)
    const int tz = threadIdx.z;            // 0..2   (tap-row group)
    const int tid = (tz * TILE_H + ty) * 24 + tx;   // 0..575

    // ---- cooperative load of padded data tile (zero-pad OOB) ----
    // Scalar, coalesced; 22*112/576 ~ 4.3 loads/thread, unrolled for MLP.
    #pragma unroll
    for (int v = 0; v < (SMEM_H * SMEM_W + NTHREADS - 1) / NTHREADS; v++) {
        const int idx = v * NTHREADS + tid;
        if (idx < SMEM_H * SMEM_W) {
            const int r  = idx / SMEM_W;
            const int cc = idx - r * SMEM_W;
            const int gh = h0 - PAD + r;
            const int gw = cc - PAD;
            float val = 0.0f;
            if ((unsigned)gh < (unsigned)HH && (unsigned)gw < (unsigned)WW)
                val = dslab[gh * WW + gw];
            tile[idx] = val;
        }
    }
    __syncthreads();

    // ---- each (x,y) thread-triple produces 4 consecutive w pixels ----
    const int w = tx * 4;                  // 0,4,...,92
    const int h = h0 + ty;
    const int t = tc / CCH;
    const int c = tc - t * CCH;

    // kernels[t, k, c, h, w] with k varying: base + k*KSTRIDE
    const float* kbase = kernels
        + ((size_t)(t * (KSZ * KSZ)) * CCH + c) * SLAB
        + (size_t)h * WW + w;

    float acc0 = 0.0f, acc1 = 0.0f, acc2 = 0.0f, acc3 = 0.0f;

    // Per-warp phase offset: desynchronize warps' tap-row sequences.
    // 18 warps/block spread over 5 phases; block hash decorrelates blocks.
    const int warp = tid >> 5;
    int off = (warp + blockIdx.x + blockIdx.y * 2) % ROWS_PER_Z;

    #pragma unroll
    for (int rr = 0; rr < ROWS_PER_Z; rr++) {
        int r = rr + off;
        if (r >= ROWS_PER_Z) r -= ROWS_PER_Z;
        const int i = tz * ROWS_PER_Z + r;       // tap row this iteration

        // data row segment: smem cols w .. w+19 (taps j=0..14 for 4 outputs)
        const float* row = &tile[(ty + i) * SMEM_W + w];
        float d[20];
        #pragma unroll
        for (int v4 = 0; v4 < 5; v4++) {
            const float4 rv = *reinterpret_cast<const float4*>(row + v4 * 4);
            d[v4 * 4 + 0] = rv.x;
            d[v4 * 4 + 1] = rv.y;
            d[v4 * 4 + 2] = rv.z;
            d[v4 * 4 + 3] = rv.w;
        }
        const float* kp = kbase + (size_t)(i * KSZ) * KSTRIDE;

        // 15 taps in 3 batches of 5 float4 loads -> MLP ~5 per warp
        #pragma unroll
        for (int b = 0; b < 3; b++) {
            float4 kv[5];
            #pragma unroll
            for (int u = 0; u < 5; u++)
                kv[u] = *reinterpret_cast<const float4*>(
                    kp + (size_t)(b * 5 + u) * KSTRIDE);
            #pragma unroll
            for (int u = 0; u < 5; u++) {
                const int j = b * 5 + u;
                acc0 = fmaf(kv[u].x, d[j + 0], acc0);
                acc1 = fmaf(kv[u].y, d[j + 1], acc1);
                acc2 = fmaf(kv[u].z, d[j + 2], acc2);
                acc3 = fmaf(kv[u].w, d[j + 3], acc3);
            }
        }
    }

    // ---- cross-z reduction through shared memory ----
    if (tz > 0) {
        part[tz - 1][ty][tx][0] = acc0;
        part[tz - 1][ty][tx][1] = acc1;
        part[tz - 1][ty][tx][2] = acc2;
        part[tz - 1][ty][tx][3] = acc3;
    }
    __syncthreads();
    if (tz == 0) {
        acc0 += part[0][ty][tx][0] + part[1][ty][tx][0];
        acc1 += part[0][ty][tx][1] + part[1][ty][tx][1];
        acc2 += part[0][ty][tx][2] + part[1][ty][tx][2];
        acc3 += part[0][ty][tx][3] + part[1][ty][tx][3];
        *reinterpret_cast<float4*>(out + (size_t)tc * SLAB + (size_t)h * WW + w)
            = make_float4(acc0, acc1, acc2, acc3);
    }
}

extern "C" void kernel_launch(void* const* d_in, const int* in_sizes, int n_in,
                              void* d_out, int out_size)
{
    // data is the small tensor (221184), kernels the big one (49766400);
    // detect by size to be robust to metadata ordering.
    const float* data;
    const float* kernels;
    if (in_sizes[0] < in_sizes[1]) {
        data    = (const float*)d_in[0];
        kernels = (const float*)d_in[1];
    } else {
        data    = (const float*)d_in[1];
        kernels = (const float*)d_in[0];
    }

    dim3 grid(HH / TILE_H, TTT * CCH);      // (12, 24) = 288 blocks, one wave
    dim3 block(24, TILE_H, ZSPLIT);         // (24, 8, 3) = 576 threads
    kpn_kernel<<<grid, block>>>(data, kernels, (float*)d_out);
}

// round 10
// speedup vs baseline: 1.2040x; 1.2040x over previous
#include <cuda_runtime.h>
#include <cstddef>

// KPN per-pixel dynamic convolution, K=15.
// data:    [1, 8, 3, 96, 96]      float32
// kernels: [1, 8, 225, 3, 96, 96] float32   (tap-major: k = i*15 + j)
// out:     [1, 8, 3, 96, 96]      float32
//
// R10 = single-CTA-per-SM retry with a LEGAL block size (R9 used 1152 > 1024).
// Block (24,16,2) = 768 threads = 24 warps; grid (6,24) = 144 blocks on
// 148 SMs -> 1 CTA/SM, no cross-CTA L1tex-queue spread. Tap rows split 8/7
// across tz (z-boundary = warp boundary, no divergence). MLP raised to 8
// float4 loads per batch so in-flight bytes match R2 (~98KB/SM).

#define KSZ    15
#define PAD    7
#define HH     96
#define WW     96
#define CCH    3
#define TTT    8
#define TILE_H 16
#define SMEM_W 112                 // 96 + 14 halo = 110 -> 112 (16B align)
#define SMEM_H (TILE_H + KSZ - 1)  // 30
#define SLAB   (HH * WW)           // 9216
#define KSTRIDE (CCH * HH * WW)    // 27648 floats between consecutive taps
#define NTHREADS (24 * TILE_H * 2) // 768

__global__ __launch_bounds__(NTHREADS, 1)
void kpn_kernel(const float* __restrict__ data,
                const float* __restrict__ kernels,
                float* __restrict__ out)
{
    __shared__ float tile[SMEM_H * SMEM_W];        // 13440 B
    __shared__ float part[TILE_H][24][4];          //  6144 B

    const int tc = blockIdx.y;             // t*3 + c, 0..23
    const int h0 = blockIdx.x * TILE_H;    // output row base
    const float* dslab = data + (size_t)tc * SLAB;

    const int tx = threadIdx.x;            // 0..23  (w / 4)
    const int ty = threadIdx.y;            // 0..15  (row in tile)
    const int tz = threadIdx.z;            // 0..1   (tap-row group: 8 / 7 rows)

    // ---- cooperative load of padded data tile (zero-pad OOB) ----
    const int tid = (tz * TILE_H + ty) * 24 + tx;   // 0..767
    #pragma unroll
    for (int v = 0; v < (SMEM_H * SMEM_W + NTHREADS - 1) / NTHREADS; v++) {
        const int idx = v * NTHREADS + tid;
        if (idx < SMEM_H * SMEM_W) {
            const int r  = idx / SMEM_W;
            const int cc = idx - r * SMEM_W;
            const int gh = h0 - PAD + r;
            const int gw = cc - PAD;
            float val = 0.0f;
            if ((unsigned)gh < (unsigned)HH && (unsigned)gw < (unsigned)WW)
                val = dslab[gh * WW + gw];
            tile[idx] = val;
        }
    }
    __syncthreads();

    // ---- each (x,y) thread-pair produces 4 consecutive w pixels ----
    const int w = tx * 4;                  // 0,4,...,92
    const int h = h0 + ty;
    const int t = tc / CCH;
    const int c = tc - t * CCH;

    // kernels[t, k, c, h, w] with k varying: base + k*KSTRIDE
    const float* kbase = kernels
        + ((size_t)(t * (KSZ * KSZ)) * CCH + c) * SLAB
        + (size_t)h * WW + w;

    float acc0 = 0.0f, acc1 = 0.0f, acc2 = 0.0f, acc3 = 0.0f;

    // tz=0: tap rows 0..7 (8 rows); tz=1: tap rows 8..14 (7 rows).
    const int nrows = 8 - tz;              // warp-uniform (tz uniform per warp)

    #pragma unroll
    for (int ii = 0; ii < 8; ii++) {
        if (ii >= nrows) break;
        const int i = tz * 8 + ii;               // global tap row 0..14

        // data row segment: smem cols w .. w+19 (taps j=0..14 for 4 outputs)
        const float* row = &tile[(ty + i) * SMEM_W + w];
        float d[20];
        #pragma unroll
        for (int v4 = 0; v4 < 5; v4++) {
            const float4 rv = *reinterpret_cast<const float4*>(row + v4 * 4);
            d[v4 * 4 + 0] = rv.x;
            d[v4 * 4 + 1] = rv.y;
            d[v4 * 4 + 2] = rv.z;
            d[v4 * 4 + 3] = rv.w;
        }
        const float* kp = kbase + (size_t)(i * KSZ) * KSTRIDE;

        // batch A: taps 0..7 -> 8 float4 loads in flight (MLP ~8)
        {
            float4 kv[8];
            #pragma unroll
            for (int u = 0; u < 8; u++)
                kv[u] = *reinterpret_cast<const float4*>(
                    kp + (size_t)u * KSTRIDE);
            #pragma unroll
            for (int u = 0; u < 8; u++) {
                acc0 = fmaf(kv[u].x, d[u + 0], acc0);
                acc1 = fmaf(kv[u].y, d[u + 1], acc1);
                acc2 = fmaf(kv[u].z, d[u + 2], acc2);
                acc3 = fmaf(kv[u].w, d[u + 3], acc3);
            }
        }
        // batch B: taps 8..14 -> 7 float4 loads in flight
        {
            float4 kv[7];
            #pragma unroll
            for (int u = 0; u < 7; u++)
                kv[u] = *reinterpret_cast<const float4*>(
                    kp + (size_t)(8 + u) * KSTRIDE);
            #pragma unroll
            for (int u = 0; u < 7; u++) {
                const int j = 8 + u;
                acc0 = fmaf(kv[u].x, d[j + 0], acc0);
                acc1 = fmaf(kv[u].y, d[j + 1], acc1);
                acc2 = fmaf(kv[u].z, d[j + 2], acc2);
                acc3 = fmaf(kv[u].w, d[j + 3], acc3);
            }
        }
    }

    // ---- cross-z reduction through shared memory ----
    if (tz == 1) {
        part[ty][tx][0] = acc0;
        part[ty][tx][1] = acc1;
        part[ty][tx][2] = acc2;
        part[ty][tx][3] = acc3;
    }
    __syncthreads();
    if (tz == 0) {
        acc0 += part[ty][tx][0];
        acc1 += part[ty][tx][1];
        acc2 += part[ty][tx][2];
        acc3 += part[ty][tx][3];
        *reinterpret_cast<float4*>(out + (size_t)tc * SLAB + (size_t)h * WW + w)
            = make_float4(acc0, acc1, acc2, acc3);
    }
}

extern "C" void kernel_launch(void* const* d_in, const int* in_sizes, int n_in,
                              void* d_out, int out_size)
{
    // data is the small tensor (221184), kernels the big one (49766400);
    // detect by size to be robust to metadata ordering.
    const float* data;
    const float* kernels;
    if (in_sizes[0] < in_sizes[1]) {
        data    = (const float*)d_in[0];
        kernels = (const float*)d_in[1];
    } else {
        data    = (const float*)d_in[1];
        kernels = (const float*)d_in[0];
    }

    dim3 grid(HH / TILE_H, TTT * CCH);      // (6, 24) = 144 blocks, 1/SM
    dim3 block(24, TILE_H, 2);              // (24, 16, 2) = 768 threads
    kpn_kernel<<<grid, block>>>(data, kernels, (float*)d_out);
}

// round 11
// speedup vs baseline: 1.2782x; 1.0616x over previous
#include <cuda_runtime.h>
#include <cstddef>

// KPN per-pixel dynamic convolution, K=15.
// data:    [1, 8, 3, 96, 96]      float32
// kernels: [1, 8, 225, 3, 96, 96] float32   (tap-major: k = i*15 + j)
// out:     [1, 8, 3, 96, 96]      float32
//
// R11 = R10 (champion, 35.3us) + pipelined prologue: tile loads go to
// registers, then the first kv batch (8 LDG.128, independent of the tile)
// issues BEFORE the STS+syncthreads, so the 200MB kernels stream starts one
// DRAM latency earlier per block. __ldcs on the stream (evict-first).

#define KSZ    15
#define PAD    7
#define HH     96
#define WW     96
#define CCH    3
#define TTT    8
#define TILE_H 16
#define SMEM_W 112                 // 96 + 14 halo = 110 -> 112 (16B align)
#define SMEM_H (TILE_H + KSZ - 1)  // 30
#define SLAB   (HH * WW)           // 9216
#define KSTRIDE (CCH * HH * WW)    // 27648 floats between consecutive taps
#define NTHREADS (24 * TILE_H * 2) // 768
#define TILE_N  (SMEM_H * SMEM_W)  // 3360
#define NLOAD   ((TILE_N + NTHREADS - 1) / NTHREADS)  // 5

__global__ __launch_bounds__(NTHREADS, 1)
void kpn_kernel(const float* __restrict__ data,
                const float* __restrict__ kernels,
                float* __restrict__ out)
{
    __shared__ float tile[TILE_N];                 // 13440 B
    __shared__ float part[TILE_H][24][4];          //  6144 B

    const int tc = blockIdx.y;             // t*3 + c, 0..23
    const int h0 = blockIdx.x * TILE_H;    // output row base
    const float* dslab = data + (size_t)tc * SLAB;

    const int tx = threadIdx.x;            // 0..23  (w / 4)
    const int ty = threadIdx.y;            // 0..15  (row in tile)
    const int tz = threadIdx.z;            // 0..1   (tap-row group: 8 / 7 rows)
    const int tid = (tz * TILE_H + ty) * 24 + tx;   // 0..767

    const int w = tx * 4;                  // 0,4,...,92
    const int h = h0 + ty;
    const int t = tc / CCH;
    const int c = tc - t * CCH;

    // kernels[t, k, c, h, w] with k varying: base + k*KSTRIDE
    const float* kbase = kernels
        + ((size_t)(t * (KSZ * KSZ)) * CCH + c) * SLAB
        + (size_t)h * WW + w;

    const int i0 = tz * 8;                 // first tap row of this z-group
    const int nrows = 8 - tz;              // 8 rows (tz=0) / 7 rows (tz=1)
    const float* kp0 = kbase + (size_t)(i0 * KSZ) * KSTRIDE;

    // ---- pipelined prologue ----
    // 1) tile gathers into registers (DRAM latency starts now)
    float tv[NLOAD];
    #pragma unroll
    for (int v = 0; v < NLOAD; v++) {
        const int idx = v * NTHREADS + tid;
        float val = 0.0f;
        if (idx < TILE_N) {
            const int r  = idx / SMEM_W;
            const int cc = idx - r * SMEM_W;
            const int gh = h0 - PAD + r;
            const int gw = cc - PAD;
            if ((unsigned)gh < (unsigned)HH && (unsigned)gw < (unsigned)WW)
                val = dslab[gh * WW + gw];
        }
        tv[v] = val;
    }
    // 2) first kv batch (independent of tile) — stream starts here
    float4 kv[8];
    #pragma unroll
    for (int u = 0; u < 8; u++)
        kv[u] = __ldcs(reinterpret_cast<const float4*>(
            kp0 + (size_t)u * KSTRIDE));
    // 3) tile stores + barrier (latency of 1+2 overlaps this wait)
    #pragma unroll
    for (int v = 0; v < NLOAD; v++) {
        const int idx = v * NTHREADS + tid;
        if (idx < TILE_N) tile[idx] = tv[v];
    }
    __syncthreads();

    float acc0 = 0.0f, acc1 = 0.0f, acc2 = 0.0f, acc3 = 0.0f;

    #pragma unroll
    for (int ii = 0; ii < 8; ii++) {
        if (ii >= nrows) break;
        const int i = i0 + ii;                   // global tap row 0..14

        // data row segment: smem cols w .. w+19 (taps j=0..14 for 4 outputs)
        const float* row = &tile[(ty + i) * SMEM_W + w];
        float d[20];
        #pragma unroll
        for (int v4 = 0; v4 < 5; v4++) {
            const float4 rv = *reinterpret_cast<const float4*>(row + v4 * 4);
            d[v4 * 4 + 0] = rv.x;
            d[v4 * 4 + 1] = rv.y;
            d[v4 * 4 + 2] = rv.z;
            d[v4 * 4 + 3] = rv.w;
        }
        const float* kp = kbase + (size_t)(i * KSZ) * KSTRIDE;

        // batch A: taps 0..7 (prefetched for ii==0)
        if (ii != 0) {
            #pragma unroll
            for (int u = 0; u < 8; u++)
                kv[u] = __ldcs(reinterpret_cast<const float4*>(
                    kp + (size_t)u * KSTRIDE));
        }
        #pragma unroll
        for (int u = 0; u < 8; u++) {
            acc0 = fmaf(kv[u].x, d[u + 0], acc0);
            acc1 = fmaf(kv[u].y, d[u + 1], acc1);
            acc2 = fmaf(kv[u].z, d[u + 2], acc2);
            acc3 = fmaf(kv[u].w, d[u + 3], acc3);
        }
        // batch B: taps 8..14
        {
            float4 kb[7];
            #pragma unroll
            for (int u = 0; u < 7; u++)
                kb[u] = __ldcs(reinterpret_cast<const float4*>(
                    kp + (size_t)(8 + u) * KSTRIDE));
            #pragma unroll
            for (int u = 0; u < 7; u++) {
                const int j = 8 + u;
                acc0 = fmaf(kb[u].x, d[j + 0], acc0);
                acc1 = fmaf(kb[u].y, d[j + 1], acc1);
                acc2 = fmaf(kb[u].z, d[j + 2], acc2);
                acc3 = fmaf(kb[u].w, d[j + 3], acc3);
            }
        }
    }

    // ---- cross-z reduction through shared memory ----
    if (tz == 1) {
        part[ty][tx][0] = acc0;
        part[ty][tx][1] = acc1;
        part[ty][tx][2] = acc2;
        part[ty][tx][3] = acc3;
    }
    __syncthreads();
    if (tz == 0) {
        acc0 += part[ty][tx][0];
        acc1 += part[ty][tx][1];
        acc2 += part[ty][tx][2];
        acc3 += part[ty][tx][3];
        *reinterpret_cast<float4*>(out + (size_t)tc * SLAB + (size_t)h * WW + w)
            = make_float4(acc0, acc1, acc2, acc3);
    }
}

extern "C" void kernel_launch(void* const* d_in, const int* in_sizes, int n_in,
                              void* d_out, int out_size)
{
    // data is the small tensor (221184), kernels the big one (49766400);
    // detect by size to be robust to metadata ordering.
    const float* data;
    const float* kernels;
    if (in_sizes[0] < in_sizes[1]) {
        data    = (const float*)d_in[0];
        kernels = (const float*)d_in[1];
    } else {
        data    = (const float*)d_in[1];
        kernels = (const float*)d_in[0];
    }

    dim3 grid(HH / TILE_H, TTT * CCH);      // (6, 24) = 144 blocks, 1/SM
    dim3 block(24, TILE_H, 2);              // (24, 16, 2) = 768 threads
    kpn_kernel<<<grid, block>>>(data, kernels, (float*)d_out);
}